// round 8
// baseline (speedup 1.0000x reference)
#include <cuda_runtime.h>
#include <cstdint>
#include <cstddef>

#define Bn 128
#define Tn 1024
#define Dn 48
#define Hn 256
#define NBLK 128
#define NTHR 256

typedef unsigned long long ull;

// ---------------- device scratch (no allocations allowed) ----------------
__device__ float g_xT[Tn * Dn * Bn];                  // [t][d][b]
__device__ float g_o0[(size_t)Tn * 2 * Hn * Bn];      // [t][512][b]  layer0 outputs
__device__ float g_gx0[(size_t)Tn * 1024 * Bn];       // canary target (dir 0)
__device__ float g_gx1[(size_t)Tn * 1024 * Bn];       // canary target (dir 1)
__device__ float g_h[2][2][Hn * Bn];                  // [parity][dir][j][b]
__device__ unsigned g_cnt_dir[2] = {0, 0};
__device__ unsigned g_rel_dir[2] = {0, 0};
__device__ unsigned g_cnt_all = 0;
__device__ unsigned g_rel_all = 0;

// ---------------- packed f32x2 helpers ----------------
__device__ __forceinline__ void ffma2(ull& d, ull a, ull b) {
    asm("fma.rn.f32x2 %0, %1, %2, %0;" : "+l"(d) : "l"(a), "l"(b));
}
__device__ __forceinline__ void fadd2(ull& d, ull a) {
    asm("add.rn.f32x2 %0, %0, %1;" : "+l"(d) : "l"(a));
}
__device__ __forceinline__ ull pack2(float a) {
    ull r;
    asm("mov.b64 %0, {%1, %1};" : "=l"(r) : "f"(a));
    return r;
}

// ---------------- cp.async helpers ----------------
__device__ __forceinline__ void cp_async16(void* smem_dst, const void* gsrc) {
    unsigned dst = (unsigned)__cvta_generic_to_shared(smem_dst);
    asm volatile("cp.async.cg.shared.global [%0], [%1], 16;" :: "r"(dst), "l"(gsrc) : "memory");
}
__device__ __forceinline__ void cp_commit() { asm volatile("cp.async.commit_group;" ::: "memory"); }
__device__ __forceinline__ void cp_wait0()  { asm volatile("cp.async.wait_group 0;"  ::: "memory"); }

// ---------------- acquire/release atomics (no MEMBAR.GPU) ----------------
__device__ __forceinline__ unsigned atom_add_acqrel(unsigned* p, unsigned v) {
    unsigned old;
    asm volatile("atom.acq_rel.gpu.add.u32 %0, [%1], %2;"
                 : "=r"(old) : "l"(p), "r"(v) : "memory");
    return old;
}
__device__ __forceinline__ void st_relaxed(unsigned* p, unsigned v) {
    asm volatile("st.relaxed.gpu.u32 [%0], %1;" :: "l"(p), "r"(v) : "memory");
}
__device__ __forceinline__ void st_release(unsigned* p, unsigned v) {
    asm volatile("st.release.gpu.u32 [%0], %1;" :: "l"(p), "r"(v) : "memory");
}
__device__ __forceinline__ unsigned ld_acquire(unsigned* p) {
    unsigned v;
    asm volatile("ld.acquire.gpu.u32 %0, [%1];" : "=r"(v) : "l"(p) : "memory");
    return v;
}

// ---------------- grid barrier (replay-safe monotonic release, acq/rel) ----------------
__device__ __forceinline__ void gbar_n(unsigned* cnt, unsigned* rel, unsigned n, unsigned& r_last) {
    __syncthreads();
    if (threadIdx.x == 0) {
        unsigned arrived = atom_add_acqrel(cnt, 1);
        if (arrived == n - 1) {
            st_relaxed(cnt, 0);                 // ordered before release store below
            st_release(rel, r_last + 1);
            r_last = r_last + 1;
        } else {
            unsigned cur;
            do { cur = ld_acquire(rel); } while (cur == r_last);
            r_last = cur;
        }
    }
    __syncthreads();
}

// ---------------- helpers ----------------
__global__ void transpose_x_kernel(const float* __restrict__ x) {
    int idx = blockIdx.x * blockDim.x + threadIdx.x;
    if (idx >= Tn * Dn * Bn) return;
    int b = idx & (Bn - 1);
    int rem = idx >> 7;
    int d = rem % Dn;
    int t = rem / Dn;
    g_xT[idx] = x[((size_t)b * Tn + t) * Dn + d];
}

__device__ __forceinline__ float sigmoidf_(float v) { return 1.0f / (1.0f + __expf(-v)); }

// ================= CANARY: x-projection GEMM, output unused =================
// Writes g_gx0/g_gx1. If this kernel corrupts memory, this round fails at 0.193986
// and the bug is located. Static smem, no opt-in needed.
#define XP_SW_STRIDE 132
template<int K, int CHUNK>
__global__ void __launch_bounds__(128) xproj_kernel(
    const float* __restrict__ Wf, const float* __restrict__ Wb,
    const float* __restrict__ bihf, const float* __restrict__ bhhf,
    const float* __restrict__ bihb, const float* __restrict__ bhhb,
    const float* __restrict__ xin)
{
    __shared__ float s_x[CHUNK * 128];
    __shared__ float s_w[CHUNK * XP_SW_STRIDE];

    const int t   = blockIdx.x;
    const int rt  = blockIdx.y;
    const int dir = blockIdx.z;
    const int tid = threadIdx.x;
    const int rg  = tid >> 3;
    const int bgp = tid & 7;

    const float* W   = dir ? Wb   : Wf;
    const float* bih = dir ? bihb : bihf;
    const float* bhh = dir ? bhhb : bhhf;
    float* gout = dir ? g_gx1 : g_gx0;

    ull acc[8][8];
#pragma unroll
    for (int u = 0; u < 8; ++u)
#pragma unroll
        for (int p = 0; p < 8; ++p) acc[u][p] = 0ull;

    const int wrow = rt * 128 + tid;
    for (int kc = 0; kc < K; kc += CHUNK) {
        const float* xsrc = xin + ((size_t)t * K + kc) * Bn;
        for (int i = tid; i < CHUNK * 32; i += 128)
            *(float4*)(s_x + i * 4) = *(const float4*)(xsrc + i * 4);
        {
            const float* wsrc = W + (size_t)wrow * K + kc;
#pragma unroll
            for (int k4 = 0; k4 < CHUNK / 4; ++k4) {
                float4 v = *(const float4*)(wsrc + k4 * 4);
                s_w[(k4 * 4 + 0) * XP_SW_STRIDE + tid] = v.x;
                s_w[(k4 * 4 + 1) * XP_SW_STRIDE + tid] = v.y;
                s_w[(k4 * 4 + 2) * XP_SW_STRIDE + tid] = v.z;
                s_w[(k4 * 4 + 3) * XP_SW_STRIDE + tid] = v.w;
            }
        }
        __syncthreads();

#pragma unroll 2
        for (int kk = 0; kk < CHUNK; ++kk) {
            float4 wa = *(const float4*)(s_w + kk * XP_SW_STRIDE + rg * 8);
            float4 wb = *(const float4*)(s_w + kk * XP_SW_STRIDE + rg * 8 + 4);
            ull w0 = pack2(wa.x), w1 = pack2(wa.y), w2 = pack2(wa.z), w3 = pack2(wa.w);
            ull w4 = pack2(wb.x), w5 = pack2(wb.y), w6 = pack2(wb.z), w7 = pack2(wb.w);
            const float* xp = s_x + kk * Bn + bgp * 16;
            ulonglong2 x0 = *(const ulonglong2*)(xp);
            ulonglong2 x1 = *(const ulonglong2*)(xp + 4);
            ulonglong2 x2 = *(const ulonglong2*)(xp + 8);
            ulonglong2 x3 = *(const ulonglong2*)(xp + 12);
            ull xv[8] = {x0.x, x0.y, x1.x, x1.y, x2.x, x2.y, x3.x, x3.y};
#define ROW(U, WV) \
            ffma2(acc[U][0], WV, xv[0]); ffma2(acc[U][1], WV, xv[1]); \
            ffma2(acc[U][2], WV, xv[2]); ffma2(acc[U][3], WV, xv[3]); \
            ffma2(acc[U][4], WV, xv[4]); ffma2(acc[U][5], WV, xv[5]); \
            ffma2(acc[U][6], WV, xv[6]); ffma2(acc[U][7], WV, xv[7]);
            ROW(0, w0) ROW(1, w1) ROW(2, w2) ROW(3, w3)
            ROW(4, w4) ROW(5, w5) ROW(6, w6) ROW(7, w7)
#undef ROW
        }
        __syncthreads();
    }

#pragma unroll
    for (int u = 0; u < 8; ++u) {
        int grow = rt * 128 + rg * 8 + u;
        ull bb = pack2(bih[grow] + bhh[grow]);
        float* dst = gout + ((size_t)t * 1024 + grow) * Bn + bgp * 16;
#pragma unroll
        for (int p = 0; p < 8; ++p) fadd2(acc[u][p], bb);
        *(ulonglong2*)(dst)      = make_ulonglong2(acc[u][0], acc[u][1]);
        *(ulonglong2*)(dst + 4)  = make_ulonglong2(acc[u][2], acc[u][3]);
        *(ulonglong2*)(dst + 8)  = make_ulonglong2(acc[u][4], acc[u][5]);
        *(ulonglong2*)(dst + 12) = make_ulonglong2(acc[u][6], acc[u][7]);
    }
}

// ================= persistent LSTM (round-4 proven, verbatim) =================
// smem layout (floats):
//   s_w    [K][16]         (K = 768 max -> 12288)   weights interleaved by row
//   s_in   [2][128][128]   (32768)
//   s_part [4][16][128]    (8192)
//   s_g    [16][128]       (2048)
//   s_bias [16] (+pad)
#define SW_OFF    0
#define SIN_OFF   (768 * 16)
#define SPART_OFF (SIN_OFF + 2 * 128 * 128)
#define SG_OFF    (SPART_OFF + 4 * 16 * 128)
#define SBIAS_OFF (SG_OFF + 16 * 128)
#define SMEM_FLOATS (SBIAS_OFF + 32)

template<int IN>
__device__ __forceinline__ void load_weights(float* s_w, const float* Wih, const float* Whh, int j0, int tid) {
    constexpr int K = IN + Hn;
    constexpr int K4 = K / 4;
    for (int i = tid; i < 16 * K4; i += NTHR) {
        int r  = i / K4;
        int gk = (i - r * K4) * 4;
        int grow = (r >> 2) * Hn + j0 + (r & 3);       // gate*H + unit
        float4 v = (gk < IN)
            ? *(const float4*)(Wih + (size_t)grow * IN + gk)
            : *(const float4*)(Whh + (size_t)grow * Hn + (gk - IN));
        s_w[(gk + 0) * 16 + r] = v.x;
        s_w[(gk + 1) * 16 + r] = v.y;
        s_w[(gk + 2) * 16 + r] = v.z;
        s_w[(gk + 3) * 16 + r] = v.w;
    }
}

template<int IN>
__device__ __forceinline__ void stage_chunk(float* sbuf, const float* xrow, const float* hread,
                                            int kc, int klen, int tid) {
    int n4 = klen * 32;                           // float4 slots (128 batch = 32 float4)
    for (int i = tid; i < n4; i += NTHR) {
        int kk = i >> 5;
        int b4 = (i & 31) * 4;
        int gk = kc + kk;
        const float* src = (gk < IN) ? (xrow + (size_t)gk * Bn + b4)
                                     : (hread + (size_t)(gk - IN) * Bn + b4);
        cp_async16(sbuf + kk * Bn + b4, src);
    }
}

template<int IN, bool L0P>
__device__ __forceinline__ void do_step(float* smem, const float* xin, int t, int dir, int j0,
                                        int tid, int len, float c_reg[2], float h_reg[2],
                                        const float* hread, float* hwrite)
{
    constexpr int K  = IN + Hn;
    constexpr int NC = (K + 127) / 128;
    float* s_w    = smem + SW_OFF;
    float* s_in   = smem + SIN_OFF;
    float* s_part = smem + SPART_OFF;
    float* s_g    = smem + SG_OFF;
    float* s_bias = smem + SBIAS_OFF;

    const int kg  = tid >> 6;            // k-group 0..3
    const int lid = tid & 63;
    const int rg  = lid >> 4;            // row group 0..3 (4 rows each)
    const int b0  = (lid & 15) * 8;      // batch base (8 batch = 4 f32x2 pairs)
    const float* xrow = xin + (size_t)t * IN * Bn;

    ull acc[4][4];
#pragma unroll
    for (int u = 0; u < 4; ++u)
#pragma unroll
        for (int p = 0; p < 4; ++p) acc[u][p] = 0ull;

    // pipeline: stage chunk 0, then wait/issue-next/consume
    stage_chunk<IN>(s_in, xrow, hread, 0, (K < 128 ? K : 128), tid);
    cp_commit();
#pragma unroll
    for (int c = 0; c < NC; ++c) {
        cp_wait0();
        __syncthreads();
        if (c + 1 < NC) {
            int kc = (c + 1) * 128;
            int kl = (K - kc < 128) ? (K - kc) : 128;
            stage_chunk<IN>(s_in + ((c + 1) & 1) * (128 * Bn), xrow, hread, kc, kl, tid);
            cp_commit();
        }
        const int klen = (K - c * 128 < 128) ? (K - c * 128) : 128;
        const int span = klen >> 2;          // k per k-group in this chunk
        const float* inb = s_in + (c & 1) * (128 * Bn);
        const int kst  = kg * span;          // within-chunk k start
        const int kbase = c * 128 + kst;     // global k start (s_w index)

#pragma unroll 4
        for (int kk = 0; kk < span; ++kk) {
            float4 wv = *(const float4*)(s_w + (size_t)(kbase + kk) * 16 + rg * 4);
            ull wa0 = pack2(wv.x);
            ull wa1 = pack2(wv.y);
            ull wa2 = pack2(wv.z);
            ull wa3 = pack2(wv.w);
            const float* ip = inb + (kst + kk) * Bn + b0;
            ulonglong2 p0 = *(const ulonglong2*)(ip);
            ulonglong2 p1 = *(const ulonglong2*)(ip + 4);
            ffma2(acc[0][0], wa0, p0.x); ffma2(acc[0][1], wa0, p0.y);
            ffma2(acc[0][2], wa0, p1.x); ffma2(acc[0][3], wa0, p1.y);
            ffma2(acc[1][0], wa1, p0.x); ffma2(acc[1][1], wa1, p0.y);
            ffma2(acc[1][2], wa1, p1.x); ffma2(acc[1][3], wa1, p1.y);
            ffma2(acc[2][0], wa2, p0.x); ffma2(acc[2][1], wa2, p0.y);
            ffma2(acc[2][2], wa2, p1.x); ffma2(acc[2][3], wa2, p1.y);
            ffma2(acc[3][0], wa3, p0.x); ffma2(acc[3][1], wa3, p0.y);
            ffma2(acc[3][2], wa3, p1.x); ffma2(acc[3][3], wa3, p1.y);
        }
    }

    // write partials: s_part[kg][r][b]  (pairs are batch-adjacent, layout matches)
#pragma unroll
    for (int u = 0; u < 4; ++u) {
        float* p = s_part + (size_t)(kg * 16 + rg * 4 + u) * Bn + b0;
        *(ulonglong2*)p       = make_ulonglong2(acc[u][0], acc[u][1]);
        *(ulonglong2*)(p + 4) = make_ulonglong2(acc[u][2], acc[u][3]);
    }
    __syncthreads();

    // reduce k-groups + bias -> s_g[r][b]
#pragma unroll
    for (int i = 0; i < 8; ++i) {
        int idx = tid + i * NTHR;
        s_g[idx] = s_bias[idx >> 7] + s_part[idx] + s_part[2048 + idx]
                 + s_part[4096 + idx] + s_part[6144 + idx];
    }
    __syncthreads();

    // pointwise LSTM update, state in registers
#pragma unroll
    for (int i = 0; i < 2; ++i) {
        int idx = tid + i * NTHR;
        int u = idx >> 7;
        int b = idx & (Bn - 1);
        float ig = sigmoidf_(s_g[(0 * 4 + u) * Bn + b]);
        float fg = sigmoidf_(s_g[(1 * 4 + u) * Bn + b]);
        float gg = tanhf    (s_g[(2 * 4 + u) * Bn + b]);
        float og = sigmoidf_(s_g[(3 * 4 + u) * Bn + b]);
        float cnew = fg * c_reg[i] + ig * gg;
        float hnew = og * tanhf(cnew);
        bool m = (t < len);
        c_reg[i] = m ? cnew : c_reg[i];
        float hw = m ? hnew : h_reg[i];
        h_reg[i] = hw;
        __stcg(&hwrite[(j0 + u) * Bn + b], hw);
        if (L0P)
            __stcg(&g_o0[((size_t)t * 2 * Hn + dir * Hn + j0 + u) * Bn + b], m ? hnew : 0.0f);
    }
}

template<int IN, bool L0P>
__device__ __forceinline__ void run_phase(float* smem,
    const float* Wih_f, const float* Whh_f, const float* bih_f, const float* bhh_f,
    const float* Wih_b, const float* Whh_b, const float* bih_b, const float* bhh_b,
    const float* xin, int dir, int j0, int tid, int len, unsigned& r_dir)
{
    const float* Wih = dir ? Wih_b : Wih_f;
    const float* Whh = dir ? Whh_b : Whh_f;
    const float* bih = dir ? bih_b : bih_f;
    const float* bhh = dir ? bhh_b : bhh_f;

    load_weights<IN>(smem + SW_OFF, Wih, Whh, j0, tid);
    if (tid < 16) {
        int grow = (tid >> 2) * Hn + j0 + (tid & 3);
        (smem + SBIAS_OFF)[tid] = bih[grow] + bhh[grow];
    }

    float c_reg[2] = {0.0f, 0.0f};
    float h_reg[2] = {0.0f, 0.0f};
#pragma unroll
    for (int i = 0; i < 2; ++i) {
        int idx = tid + i * NTHR;
        int u = idx >> 7;
        int b = idx & (Bn - 1);
        __stcg(&g_h[0][dir][(j0 + u) * Bn + b], 0.0f);
        __stcg(&g_h[1][dir][(j0 + u) * Bn + b], 0.0f);
    }
    gbar_n(&g_cnt_dir[dir], &g_rel_dir[dir], NBLK / 2, r_dir);

    for (int s = 0; s < Tn; ++s) {
        int t = dir ? (Tn - 1 - s) : s;
        const float* hread  = g_h[s & 1][dir];
        float*       hwrite = g_h[(s + 1) & 1][dir];
        do_step<IN, L0P>(smem, xin, t, dir, j0, tid, len, c_reg, h_reg, hread, hwrite);
        gbar_n(&g_cnt_dir[dir], &g_rel_dir[dir], NBLK / 2, r_dir);
    }
}

__global__ void __launch_bounds__(NTHR, 1) lstm_persistent_kernel(
    const float* __restrict__ w_ih_l0f, const float* __restrict__ w_hh_l0f,
    const float* __restrict__ b_ih_l0f, const float* __restrict__ b_hh_l0f,
    const float* __restrict__ w_ih_l0b, const float* __restrict__ w_hh_l0b,
    const float* __restrict__ b_ih_l0b, const float* __restrict__ b_hh_l0b,
    const float* __restrict__ w_ih_l1f, const float* __restrict__ w_hh_l1f,
    const float* __restrict__ b_ih_l1f, const float* __restrict__ b_hh_l1f,
    const float* __restrict__ w_ih_l1b, const float* __restrict__ w_hh_l1b,
    const float* __restrict__ b_ih_l1b, const float* __restrict__ b_hh_l1b,
    const int* __restrict__ lengths)
{
    extern __shared__ float smem[];
    const int tid = threadIdx.x;
    const int dir = blockIdx.x >> 6;           // 0..1
    const int j0  = (blockIdx.x & 63) * 4;     // 4 hidden units per block
    const int len = lengths[tid & (Bn - 1)];

    unsigned r_dir = ld_acquire(&g_rel_dir[dir]);
    unsigned r_all = ld_acquire(&g_rel_all);

    run_phase<Dn, true>(smem,
        w_ih_l0f, w_hh_l0f, b_ih_l0f, b_hh_l0f,
        w_ih_l0b, w_hh_l0b, b_ih_l0b, b_hh_l0b,
        g_xT, dir, j0, tid, len, r_dir);

    // phase boundary: L1 consumes g_o0 from BOTH directions
    gbar_n(&g_cnt_all, &g_rel_all, NBLK, r_all);

    run_phase<2 * Hn, false>(smem,
        w_ih_l1f, w_hh_l1f, b_ih_l1f, b_hh_l1f,
        w_ih_l1b, w_hh_l1b, b_ih_l1b, b_hh_l1b,
        g_o0, dir, j0, tid, len, r_dir);
}

// ---------------- FC head ----------------
__global__ void head_kernel(const float* __restrict__ fc1_w, const float* __restrict__ fc1_b,
                            const float* __restrict__ fc2_w, const float* __restrict__ fc2_b,
                            float* __restrict__ out)
{
    __shared__ float s_h[2 * Hn];
    __shared__ float s_r[256];
    int b = blockIdx.x;
    int tid = threadIdx.x;
    // final L1 states: 1024 steps -> parity 0
    for (int k = tid; k < 2 * Hn; k += 256)
        s_h[k] = (k < Hn) ? g_h[0][0][k * Bn + b] : g_h[0][1][(k - Hn) * Bn + b];
    __syncthreads();

    const float* wr = fc1_w + (size_t)tid * 2 * Hn;
    float sum = fc1_b[tid];
#pragma unroll 8
    for (int k = 0; k < 2 * Hn; ++k) sum += wr[k] * s_h[k];
    s_r[tid] = fmaxf(sum, 0.0f) * fc2_w[tid];
    __syncthreads();
    for (int st = 128; st > 0; st >>= 1) {
        if (tid < st) s_r[tid] += s_r[tid + st];
        __syncthreads();
    }
    if (tid == 0) out[b] = s_r[0] + fc2_b[0];
}

// ---------------- launch ----------------
extern "C" void kernel_launch(void* const* d_in, const int* in_sizes, int n_in,
                              void* d_out, int out_size)
{
    const float* x        = (const float*)d_in[0];
    const int*   lengths  = (const int*)  d_in[1];
    const float* w_ih_l0f = (const float*)d_in[2];
    const float* w_hh_l0f = (const float*)d_in[3];
    const float* b_ih_l0f = (const float*)d_in[4];
    const float* b_hh_l0f = (const float*)d_in[5];
    const float* w_ih_l0b = (const float*)d_in[6];
    const float* w_hh_l0b = (const float*)d_in[7];
    const float* b_ih_l0b = (const float*)d_in[8];
    const float* b_hh_l0b = (const float*)d_in[9];
    const float* w_ih_l1f = (const float*)d_in[10];
    const float* w_hh_l1f = (const float*)d_in[11];
    const float* b_ih_l1f = (const float*)d_in[12];
    const float* b_hh_l1f = (const float*)d_in[13];
    const float* w_ih_l1b = (const float*)d_in[14];
    const float* w_hh_l1b = (const float*)d_in[15];
    const float* b_ih_l1b = (const float*)d_in[16];
    const float* b_hh_l1b = (const float*)d_in[17];
    const float* fc1_w    = (const float*)d_in[18];
    const float* fc1_b    = (const float*)d_in[19];
    const float* fc2_w    = (const float*)d_in[20];
    const float* fc2_b    = (const float*)d_in[21];

    const size_t smem_bytes = (size_t)SMEM_FLOATS * sizeof(float);   // ~216 KB
    cudaFuncSetAttribute((const void*)lstm_persistent_kernel,
                         cudaFuncAttributeMaxDynamicSharedMemorySize, (int)smem_bytes);

    transpose_x_kernel<<<(Tn * Dn * Bn + 255) / 256, 256>>>(x);

    // ---- CANARY: xproj L0, output unused (diagnoses the rounds 5-7 failure) ----
    dim3 xpgrid(Tn, 8, 2);
    xproj_kernel<48, 16><<<xpgrid, 128>>>(
        w_ih_l0f, w_ih_l0b, b_ih_l0f, b_hh_l0f, b_ih_l0b, b_hh_l0b, g_xT);

    lstm_persistent_kernel<<<NBLK, NTHR, smem_bytes>>>(
        w_ih_l0f, w_hh_l0f, b_ih_l0f, b_hh_l0f,
        w_ih_l0b, w_hh_l0b, b_ih_l0b, b_hh_l0b,
        w_ih_l1f, w_hh_l1f, b_ih_l1f, b_hh_l1f,
        w_ih_l1b, w_hh_l1b, b_ih_l1b, b_hh_l1b,
        lengths);

    head_kernel<<<Bn, 256>>>(fc1_w, fc1_b, fc2_w, fc2_b, (float*)d_out);
}

// round 10
// speedup vs baseline: 1.1227x; 1.1227x over previous
#include <cuda_runtime.h>
#include <cstdint>
#include <cstddef>

#define Bn 128
#define Tn 1024
#define Dn 48
#define Hn 256
#define NBLK 128
#define NTHR 256

typedef unsigned long long ull;

// ---------------- device scratch (no allocations allowed) ----------------
__device__ float g_xT[Tn * Dn * Bn];                  // [t][48][b]
__device__ float g_o0[(size_t)Tn * 2 * Hn * Bn];      // [t][512][b]  layer0 outputs
__device__ float g_gx0[(size_t)Tn * 1024 * Bn];       // x-projection, dir 0 (incl. both biases)
__device__ float g_gx1[(size_t)Tn * 1024 * Bn];       // x-projection, dir 1
__device__ float g_h[2][2][Hn * Bn];                  // [parity][dir][j][b]
__device__ unsigned g_cnt_dir[2] = {0, 0};
__device__ unsigned g_rel_dir[2] = {0, 0};

// ---------------- packed f32x2 helpers ----------------
__device__ __forceinline__ void ffma2(ull& d, ull a, ull b) {
    asm("fma.rn.f32x2 %0, %1, %2, %0;" : "+l"(d) : "l"(a), "l"(b));
}
__device__ __forceinline__ void fadd2(ull& d, ull a) {
    asm("add.rn.f32x2 %0, %0, %1;" : "+l"(d) : "l"(a));
}
__device__ __forceinline__ ull pack2(float a) {
    ull r;
    asm("mov.b64 %0, {%1, %1};" : "=l"(r) : "f"(a));
    return r;
}

// ---------------- cp.async helpers ----------------
__device__ __forceinline__ void cp_async16(void* smem_dst, const void* gsrc) {
    unsigned dst = (unsigned)__cvta_generic_to_shared(smem_dst);
    asm volatile("cp.async.cg.shared.global [%0], [%1], 16;" :: "r"(dst), "l"(gsrc) : "memory");
}
__device__ __forceinline__ void cp_commit() { asm volatile("cp.async.commit_group;" ::: "memory"); }
__device__ __forceinline__ void cp_wait0()  { asm volatile("cp.async.wait_group 0;"  ::: "memory"); }

// ---------------- acquire/release atomics ----------------
__device__ __forceinline__ unsigned atom_add_acqrel(unsigned* p, unsigned v) {
    unsigned old;
    asm volatile("atom.acq_rel.gpu.add.u32 %0, [%1], %2;"
                 : "=r"(old) : "l"(p), "r"(v) : "memory");
    return old;
}
__device__ __forceinline__ void st_relaxed(unsigned* p, unsigned v) {
    asm volatile("st.relaxed.gpu.u32 [%0], %1;" :: "l"(p), "r"(v) : "memory");
}
__device__ __forceinline__ void st_release(unsigned* p, unsigned v) {
    asm volatile("st.release.gpu.u32 [%0], %1;" :: "l"(p), "r"(v) : "memory");
}
__device__ __forceinline__ unsigned ld_acquire(unsigned* p) {
    unsigned v;
    asm volatile("ld.acquire.gpu.u32 %0, [%1];" : "=r"(v) : "l"(p) : "memory");
    return v;
}

// ---------------- grid barrier (replay-safe monotonic release, acq/rel) ----------------
__device__ __forceinline__ void gbar_n(unsigned* cnt, unsigned* rel, unsigned n, unsigned& r_last) {
    __syncthreads();
    if (threadIdx.x == 0) {
        unsigned arrived = atom_add_acqrel(cnt, 1);
        if (arrived == n - 1) {
            st_relaxed(cnt, 0);
            st_release(rel, r_last + 1);
            r_last = r_last + 1;
        } else {
            unsigned cur;
            do { cur = ld_acquire(rel); } while (cur == r_last);
            r_last = cur;
        }
    }
    __syncthreads();
}

// ---------------- transpose x ----------------
__global__ void transpose_x_kernel(const float* __restrict__ x) {
    int idx = blockIdx.x * blockDim.x + threadIdx.x;
    if (idx >= Tn * Dn * Bn) return;
    int b = idx & (Bn - 1);
    int rem = idx >> 7;
    int d = rem % Dn;
    int t = rem / Dn;
    g_xT[idx] = x[((size_t)b * Tn + t) * Dn + d];
}

__device__ __forceinline__ float sigmoidf_(float v) { return 1.0f / (1.0f + __expf(-v)); }

// ================= x-projection GEMM =================
// CRITICAL FIX: the source tensor is selected IN DEVICE CODE (template), never
// passed as a host-side argument — passing a __device__ symbol from host code
// passes the host shadow stub's address, which GB300's ATS dereferences to host
// zeros WITHOUT faulting (the rounds 5-9 bug).
#define XP_SW_STRIDE 132
template<int K, int CHUNK, bool SRC_O0>
__global__ void __launch_bounds__(128) xproj_kernel(
    const float* __restrict__ Wf, const float* __restrict__ Wb,
    const float* __restrict__ bihf, const float* __restrict__ bhhf,
    const float* __restrict__ bihb, const float* __restrict__ bhhb)
{
    __shared__ float s_x[CHUNK * 128];
    __shared__ float s_w[CHUNK * XP_SW_STRIDE];

    const float* xin = SRC_O0 ? g_o0 : g_xT;     // device-side symbol resolution

    const int t   = blockIdx.x;
    const int rt  = blockIdx.y;
    const int dir = blockIdx.z;
    const int tid = threadIdx.x;
    const int rg  = tid >> 3;
    const int bgp = tid & 7;

    const float* W   = dir ? Wb   : Wf;
    const float* bih = dir ? bihb : bihf;
    const float* bhh = dir ? bhhb : bhhf;
    float* gout = dir ? g_gx1 : g_gx0;

    ull acc[8][8];
#pragma unroll
    for (int u = 0; u < 8; ++u)
#pragma unroll
        for (int p = 0; p < 8; ++p) acc[u][p] = 0ull;

    const int wrow = rt * 128 + tid;
    for (int kc = 0; kc < K; kc += CHUNK) {
        const float* xsrc = xin + ((size_t)t * K + kc) * Bn;
        for (int i = tid; i < CHUNK * 32; i += 128)
            *(float4*)(s_x + i * 4) = *(const float4*)(xsrc + i * 4);
        {
            const float* wsrc = W + (size_t)wrow * K + kc;
#pragma unroll
            for (int k4 = 0; k4 < CHUNK / 4; ++k4) {
                float4 v = *(const float4*)(wsrc + k4 * 4);
                s_w[(k4 * 4 + 0) * XP_SW_STRIDE + tid] = v.x;
                s_w[(k4 * 4 + 1) * XP_SW_STRIDE + tid] = v.y;
                s_w[(k4 * 4 + 2) * XP_SW_STRIDE + tid] = v.z;
                s_w[(k4 * 4 + 3) * XP_SW_STRIDE + tid] = v.w;
            }
        }
        __syncthreads();

#pragma unroll 2
        for (int kk = 0; kk < CHUNK; ++kk) {
            float4 wa = *(const float4*)(s_w + kk * XP_SW_STRIDE + rg * 8);
            float4 wb = *(const float4*)(s_w + kk * XP_SW_STRIDE + rg * 8 + 4);
            ull w0 = pack2(wa.x), w1 = pack2(wa.y), w2 = pack2(wa.z), w3 = pack2(wa.w);
            ull w4 = pack2(wb.x), w5 = pack2(wb.y), w6 = pack2(wb.z), w7 = pack2(wb.w);
            const float* xp = s_x + kk * Bn + bgp * 16;
            ulonglong2 x0 = *(const ulonglong2*)(xp);
            ulonglong2 x1 = *(const ulonglong2*)(xp + 4);
            ulonglong2 x2 = *(const ulonglong2*)(xp + 8);
            ulonglong2 x3 = *(const ulonglong2*)(xp + 12);
            ull xv[8] = {x0.x, x0.y, x1.x, x1.y, x2.x, x2.y, x3.x, x3.y};
#define ROW(U, WV) \
            ffma2(acc[U][0], WV, xv[0]); ffma2(acc[U][1], WV, xv[1]); \
            ffma2(acc[U][2], WV, xv[2]); ffma2(acc[U][3], WV, xv[3]); \
            ffma2(acc[U][4], WV, xv[4]); ffma2(acc[U][5], WV, xv[5]); \
            ffma2(acc[U][6], WV, xv[6]); ffma2(acc[U][7], WV, xv[7]);
            ROW(0, w0) ROW(1, w1) ROW(2, w2) ROW(3, w3)
            ROW(4, w4) ROW(5, w5) ROW(6, w6) ROW(7, w7)
#undef ROW
        }
        __syncthreads();
    }

#pragma unroll
    for (int u = 0; u < 8; ++u) {
        int grow = rt * 128 + rg * 8 + u;
        ull bb = pack2(bih[grow] + bhh[grow]);
        float* dst = gout + ((size_t)t * 1024 + grow) * Bn + bgp * 16;
#pragma unroll
        for (int p = 0; p < 8; ++p) fadd2(acc[u][p], bb);
        *(ulonglong2*)(dst)      = make_ulonglong2(acc[u][0], acc[u][1]);
        *(ulonglong2*)(dst + 4)  = make_ulonglong2(acc[u][2], acc[u][3]);
        *(ulonglong2*)(dst + 8)  = make_ulonglong2(acc[u][4], acc[u][5]);
        *(ulonglong2*)(dst + 12) = make_ulonglong2(acc[u][6], acc[u][7]);
    }
}

// ================= persistent LSTM recurrence (r8-proven machinery, GX mode) =================
// smem (floats): s_w [256][16]; s_in [2][128][128]; s_part [4][16][128];
//                s_g [16][128]; pad [32]; s_gx [16][128]
#define RC_K 256
#define RC_SMEM_FLOATS (RC_K * 16 + 2 * 128 * Bn + 4 * 16 * Bn + 16 * Bn + 32 + 16 * Bn)

__device__ __forceinline__ void load_weights_hh(float* s_w, const float* Whh, int j0, int tid) {
    for (int i = tid; i < 16 * 64; i += NTHR) {
        int r  = i >> 6;
        int gk = (i & 63) * 4;
        int grow = (r >> 2) * Hn + j0 + (r & 3);       // gate*H + unit
        float4 v = *(const float4*)(Whh + (size_t)grow * Hn + gk);
        s_w[(gk + 0) * 16 + r] = v.x;
        s_w[(gk + 1) * 16 + r] = v.y;
        s_w[(gk + 2) * 16 + r] = v.z;
        s_w[(gk + 3) * 16 + r] = v.w;
    }
}

template<bool L0P>
__device__ __forceinline__ void do_step(float* smem, const float* gxrow,
                                        int t, int dir, int j0,
                                        int tid, int len, float c_reg[2], float h_reg[2],
                                        const float* hread, float* hwrite)
{
    float* s_w    = smem;
    float* s_in   = smem + RC_K * 16;
    float* s_part = s_in + 2 * 128 * Bn;
    float* s_g    = s_part + 4 * 16 * Bn;
    float* s_gx   = s_g + 16 * Bn + 32;

    const int kg  = tid >> 6;            // k-group 0..3
    const int lid = tid & 63;
    const int rg  = lid >> 4;            // gate 0..3 (4 rows each)
    const int b0  = (lid & 15) * 8;      // batch base

    ull acc[4][4];
#pragma unroll
    for (int u = 0; u < 4; ++u)
#pragma unroll
        for (int p = 0; p < 4; ++p) acc[u][p] = 0ull;

    // stage gx rows + h chunk 0; then h chunk 1 (proven structure)
    for (int i = tid; i < 512; i += NTHR) {
        int r = i >> 5, b4 = (i & 31) * 4;
        int grow = (r >> 2) * Hn + j0 + (r & 3);
        cp_async16(s_gx + r * Bn + b4, gxrow + (size_t)grow * Bn + b4);
    }
    for (int i = tid; i < 4096; i += NTHR)
        cp_async16(s_in + i * 4, hread + i * 4);
    cp_commit();
#pragma unroll
    for (int c = 0; c < 2; ++c) {
        cp_wait0();
        __syncthreads();
        if (c == 0) {
            for (int i = tid; i < 4096; i += NTHR)
                cp_async16(s_in + 128 * Bn + i * 4, hread + 16384 + i * 4);
            cp_commit();
        }
        const float* inb = s_in + c * (128 * Bn);
        const int kst  = kg * 32;
        const int kbase = c * 128 + kst;

#pragma unroll 4
        for (int kk = 0; kk < 32; ++kk) {
            float4 wv = *(const float4*)(s_w + (size_t)(kbase + kk) * 16 + rg * 4);
            ull wa0 = pack2(wv.x);
            ull wa1 = pack2(wv.y);
            ull wa2 = pack2(wv.z);
            ull wa3 = pack2(wv.w);
            const float* ip = inb + (kst + kk) * Bn + b0;
            ulonglong2 p0 = *(const ulonglong2*)(ip);
            ulonglong2 p1 = *(const ulonglong2*)(ip + 4);
            ffma2(acc[0][0], wa0, p0.x); ffma2(acc[0][1], wa0, p0.y);
            ffma2(acc[0][2], wa0, p1.x); ffma2(acc[0][3], wa0, p1.y);
            ffma2(acc[1][0], wa1, p0.x); ffma2(acc[1][1], wa1, p0.y);
            ffma2(acc[1][2], wa1, p1.x); ffma2(acc[1][3], wa1, p1.y);
            ffma2(acc[2][0], wa2, p0.x); ffma2(acc[2][1], wa2, p0.y);
            ffma2(acc[2][2], wa2, p1.x); ffma2(acc[2][3], wa2, p1.y);
            ffma2(acc[3][0], wa3, p0.x); ffma2(acc[3][1], wa3, p0.y);
            ffma2(acc[3][2], wa3, p1.x); ffma2(acc[3][3], wa3, p1.y);
        }
    }

    // partials: s_part[kg][r][b]
#pragma unroll
    for (int u = 0; u < 4; ++u) {
        float* p = s_part + (size_t)(kg * 16 + rg * 4 + u) * Bn + b0;
        *(ulonglong2*)p       = make_ulonglong2(acc[u][0], acc[u][1]);
        *(ulonglong2*)(p + 4) = make_ulonglong2(acc[u][2], acc[u][3]);
    }
    __syncthreads();

    // reduce k-groups + gx (biases folded into gx)
#pragma unroll
    for (int i = 0; i < 8; ++i) {
        int idx = tid + i * NTHR;
        s_g[idx] = s_gx[idx] + s_part[idx] + s_part[2048 + idx]
                 + s_part[4096 + idx] + s_part[6144 + idx];
    }
    __syncthreads();

    // pointwise LSTM update
#pragma unroll
    for (int i = 0; i < 2; ++i) {
        int idx = tid + i * NTHR;
        int u = idx >> 7;
        int b = idx & (Bn - 1);
        float ig = sigmoidf_(s_g[(0 * 4 + u) * Bn + b]);
        float fg = sigmoidf_(s_g[(1 * 4 + u) * Bn + b]);
        float gg = tanhf    (s_g[(2 * 4 + u) * Bn + b]);
        float og = sigmoidf_(s_g[(3 * 4 + u) * Bn + b]);
        float cnew = fg * c_reg[i] + ig * gg;
        float hnew = og * tanhf(cnew);
        bool m = (t < len);
        c_reg[i] = m ? cnew : c_reg[i];
        float hw = m ? hnew : h_reg[i];
        h_reg[i] = hw;
        __stcg(&hwrite[(j0 + u) * Bn + b], hw);
        if (L0P)
            __stcg(&g_o0[((size_t)t * 2 * Hn + dir * Hn + j0 + u) * Bn + b], m ? hnew : 0.0f);
    }
}

template<bool L0P>
__device__ __forceinline__ void run_phase(float* smem, const float* Whh,
                                          int dir, int j0, int tid, int len, unsigned& r_dir)
{
    load_weights_hh(smem, Whh, j0, tid);

    float c_reg[2] = {0.0f, 0.0f};
    float h_reg[2] = {0.0f, 0.0f};
#pragma unroll
    for (int i = 0; i < 2; ++i) {
        int idx = tid + i * NTHR;
        int u = idx >> 7;
        int b = idx & (Bn - 1);
        __stcg(&g_h[0][dir][(j0 + u) * Bn + b], 0.0f);
        __stcg(&g_h[1][dir][(j0 + u) * Bn + b], 0.0f);
    }
    gbar_n(&g_cnt_dir[dir], &g_rel_dir[dir], NBLK / 2, r_dir);

    const float* gxb = dir ? g_gx1 : g_gx0;
    for (int s = 0; s < Tn; ++s) {
        int t = dir ? (Tn - 1 - s) : s;
        const float* hread  = g_h[s & 1][dir];
        float*       hwrite = g_h[(s + 1) & 1][dir];
        do_step<L0P>(smem, gxb + (size_t)t * 1024 * Bn, t, dir, j0, tid, len,
                     c_reg, h_reg, hread, hwrite);
        gbar_n(&g_cnt_dir[dir], &g_rel_dir[dir], NBLK / 2, r_dir);
    }
}

__global__ void __launch_bounds__(NTHR, 1) lstm_l0_kernel(
    const float* __restrict__ w_hh_l0f, const float* __restrict__ w_hh_l0b,
    const int* __restrict__ lengths)
{
    extern __shared__ float smem[];
    const int tid = threadIdx.x;
    const int dir = blockIdx.x >> 6;
    const int j0  = (blockIdx.x & 63) * 4;
    const int len = lengths[tid & (Bn - 1)];
    unsigned r_dir = ld_acquire(&g_rel_dir[dir]);
    run_phase<true>(smem, dir ? w_hh_l0b : w_hh_l0f, dir, j0, tid, len, r_dir);
}

__global__ void __launch_bounds__(NTHR, 1) lstm_l1_kernel(
    const float* __restrict__ w_hh_l1f, const float* __restrict__ w_hh_l1b,
    const int* __restrict__ lengths)
{
    extern __shared__ float smem[];
    const int tid = threadIdx.x;
    const int dir = blockIdx.x >> 6;
    const int j0  = (blockIdx.x & 63) * 4;
    const int len = lengths[tid & (Bn - 1)];
    unsigned r_dir = ld_acquire(&g_rel_dir[dir]);
    run_phase<false>(smem, dir ? w_hh_l1b : w_hh_l1f, dir, j0, tid, len, r_dir);
}

// ---------------- FC head ----------------
__global__ void head_kernel(const float* __restrict__ fc1_w, const float* __restrict__ fc1_b,
                            const float* __restrict__ fc2_w, const float* __restrict__ fc2_b,
                            float* __restrict__ out)
{
    __shared__ float s_h[2 * Hn];
    __shared__ float s_r[256];
    int b = blockIdx.x;
    int tid = threadIdx.x;
    // final L1 states: 1024 steps -> parity 0
    for (int k = tid; k < 2 * Hn; k += 256)
        s_h[k] = (k < Hn) ? g_h[0][0][k * Bn + b] : g_h[0][1][(k - Hn) * Bn + b];
    __syncthreads();

    const float* wr = fc1_w + (size_t)tid * 2 * Hn;
    float sum = fc1_b[tid];
#pragma unroll 8
    for (int k = 0; k < 2 * Hn; ++k) sum += wr[k] * s_h[k];
    s_r[tid] = fmaxf(sum, 0.0f) * fc2_w[tid];
    __syncthreads();
    for (int st = 128; st > 0; st >>= 1) {
        if (tid < st) s_r[tid] += s_r[tid + st];
        __syncthreads();
    }
    if (tid == 0) out[b] = s_r[0] + fc2_b[0];
}

// ---------------- launch ----------------
extern "C" void kernel_launch(void* const* d_in, const int* in_sizes, int n_in,
                              void* d_out, int out_size)
{
    const float* x        = (const float*)d_in[0];
    const int*   lengths  = (const int*)  d_in[1];
    const float* w_ih_l0f = (const float*)d_in[2];
    const float* w_hh_l0f = (const float*)d_in[3];
    const float* b_ih_l0f = (const float*)d_in[4];
    const float* b_hh_l0f = (const float*)d_in[5];
    const float* w_ih_l0b = (const float*)d_in[6];
    const float* w_hh_l0b = (const float*)d_in[7];
    const float* b_ih_l0b = (const float*)d_in[8];
    const float* b_hh_l0b = (const float*)d_in[9];
    const float* w_ih_l1f = (const float*)d_in[10];
    const float* w_hh_l1f = (const float*)d_in[11];
    const float* b_ih_l1f = (const float*)d_in[12];
    const float* b_hh_l1f = (const float*)d_in[13];
    const float* w_ih_l1b = (const float*)d_in[14];
    const float* w_hh_l1b = (const float*)d_in[15];
    const float* b_ih_l1b = (const float*)d_in[16];
    const float* b_hh_l1b = (const float*)d_in[17];
    const float* fc1_w    = (const float*)d_in[18];
    const float* fc1_b    = (const float*)d_in[19];
    const float* fc2_w    = (const float*)d_in[20];
    const float* fc2_b    = (const float*)d_in[21];

    const int rec_smem = RC_SMEM_FLOATS * (int)sizeof(float);   // ~188 KB

    cudaFuncSetAttribute((const void*)lstm_l0_kernel,
                         cudaFuncAttributeMaxDynamicSharedMemorySize, rec_smem);
    cudaFuncSetAttribute((const void*)lstm_l1_kernel,
                         cudaFuncAttributeMaxDynamicSharedMemorySize, rec_smem);

    transpose_x_kernel<<<(Tn * Dn * Bn + 255) / 256, 256>>>(x);

    dim3 xpgrid(Tn, 8, 2);

    // layer-0 x-projection: g_xT -> g_gx (device-resolved source)
    xproj_kernel<48, 16, false><<<xpgrid, 128>>>(
        w_ih_l0f, w_ih_l0b, b_ih_l0f, b_hh_l0f, b_ih_l0b, b_hh_l0b);

    // layer-0 recurrence (h-only, consumes gx, writes g_o0)
    lstm_l0_kernel<<<NBLK, NTHR, rec_smem>>>(w_hh_l0f, w_hh_l0b, lengths);

    // layer-1 x-projection: g_o0 -> g_gx
    xproj_kernel<512, 32, true><<<xpgrid, 128>>>(
        w_ih_l1f, w_ih_l1b, b_ih_l1f, b_hh_l1f, b_ih_l1b, b_hh_l1b);

    // layer-1 recurrence (h-only, consumes gx)
    lstm_l1_kernel<<<NBLK, NTHR, rec_smem>>>(w_hh_l1f, w_hh_l1b, lengths);

    head_kernel<<<Bn, 256>>>(fc1_w, fc1_b, fc2_w, fc2_b, (float*)d_out);
}

// round 11
// speedup vs baseline: 1.3408x; 1.1943x over previous
#include <cuda_runtime.h>
#include <cstdint>
#include <cstddef>

#define Bn 128
#define Tn 1024
#define Dn 48
#define Hn 256
#define NBLK 128
#define NTHR 256

typedef unsigned long long ull;

// ---------------- device scratch (no allocations allowed) ----------------
__device__ float g_xT[Tn * Dn * Bn];                  // [t][48][b]
__device__ float g_o0[(size_t)Tn * 2 * Hn * Bn];      // [t][512][b]  layer0 outputs
__device__ float g_gx0[(size_t)Tn * 1024 * Bn];       // x-projection, dir 0 (incl. both biases)
__device__ float g_gx1[(size_t)Tn * 1024 * Bn];       // x-projection, dir 1
__device__ float g_h[2][2][8][Hn * 16];               // [parity][dir][bg][k*16 + b]
__device__ unsigned g_cntg[16];
__device__ unsigned g_relg[16];

// ---------------- packed f32x2 helpers ----------------
__device__ __forceinline__ void ffma2(ull& d, ull a, ull b) {
    asm("fma.rn.f32x2 %0, %1, %2, %0;" : "+l"(d) : "l"(a), "l"(b));
}
__device__ __forceinline__ void fadd2(ull& d, ull a) {
    asm("add.rn.f32x2 %0, %0, %1;" : "+l"(d) : "l"(a));
}
__device__ __forceinline__ ull pack2(float a) {
    ull r;
    asm("mov.b64 %0, {%1, %1};" : "=l"(r) : "f"(a));
    return r;
}

// ---------------- cp.async helpers ----------------
__device__ __forceinline__ void cp_async16(void* smem_dst, const void* gsrc) {
    unsigned dst = (unsigned)__cvta_generic_to_shared(smem_dst);
    asm volatile("cp.async.cg.shared.global [%0], [%1], 16;" :: "r"(dst), "l"(gsrc) : "memory");
}
__device__ __forceinline__ void cp_commit() { asm volatile("cp.async.commit_group;" ::: "memory"); }
__device__ __forceinline__ void cp_wait0()  { asm volatile("cp.async.wait_group 0;"  ::: "memory"); }

// ---------------- acquire/release atomics ----------------
__device__ __forceinline__ unsigned atom_add_acqrel(unsigned* p, unsigned v) {
    unsigned old;
    asm volatile("atom.acq_rel.gpu.add.u32 %0, [%1], %2;"
                 : "=r"(old) : "l"(p), "r"(v) : "memory");
    return old;
}
__device__ __forceinline__ void st_relaxed(unsigned* p, unsigned v) {
    asm volatile("st.relaxed.gpu.u32 [%0], %1;" :: "l"(p), "r"(v) : "memory");
}
__device__ __forceinline__ void st_release(unsigned* p, unsigned v) {
    asm volatile("st.release.gpu.u32 [%0], %1;" :: "l"(p), "r"(v) : "memory");
}
__device__ __forceinline__ unsigned ld_acquire(unsigned* p) {
    unsigned v;
    asm volatile("ld.acquire.gpu.u32 %0, [%1];" : "=r"(v) : "l"(p) : "memory");
    return v;
}

// ---------------- group barrier (8 blocks; replay-safe monotonic release) ----------------
__device__ __forceinline__ void gbar_grp(int grp, unsigned& r_last) {
    __syncthreads();
    if (threadIdx.x == 0) {
        unsigned arrived = atom_add_acqrel(&g_cntg[grp], 1);
        if (arrived == 7) {
            st_relaxed(&g_cntg[grp], 0);
            st_release(&g_relg[grp], r_last + 1);
            r_last = r_last + 1;
        } else {
            unsigned cur;
            do { cur = ld_acquire(&g_relg[grp]); } while (cur == r_last);
            r_last = cur;
        }
    }
    __syncthreads();
}

// ---------------- transpose x ----------------
__global__ void transpose_x_kernel(const float* __restrict__ x) {
    int idx = blockIdx.x * blockDim.x + threadIdx.x;
    if (idx >= Tn * Dn * Bn) return;
    int b = idx & (Bn - 1);
    int rem = idx >> 7;
    int d = rem % Dn;
    int t = rem / Dn;
    g_xT[idx] = x[((size_t)b * Tn + t) * Dn + d];
}

__device__ __forceinline__ float sigmoidf_(float v) { return 1.0f / (1.0f + __expf(-v)); }

// ================= x-projection GEMM (r10-proven, device-resolved source) =================
#define XP_SW_STRIDE 132
template<int K, int CHUNK, bool SRC_O0>
__global__ void __launch_bounds__(128) xproj_kernel(
    const float* __restrict__ Wf, const float* __restrict__ Wb,
    const float* __restrict__ bihf, const float* __restrict__ bhhf,
    const float* __restrict__ bihb, const float* __restrict__ bhhb)
{
    __shared__ float s_x[CHUNK * 128];
    __shared__ float s_w[CHUNK * XP_SW_STRIDE];

    const float* xin = SRC_O0 ? g_o0 : g_xT;     // device-side symbol resolution

    const int t   = blockIdx.x;
    const int rt  = blockIdx.y;
    const int dir = blockIdx.z;
    const int tid = threadIdx.x;
    const int rg  = tid >> 3;
    const int bgp = tid & 7;

    const float* W   = dir ? Wb   : Wf;
    const float* bih = dir ? bihb : bihf;
    const float* bhh = dir ? bhhb : bhhf;
    float* gout = dir ? g_gx1 : g_gx0;

    ull acc[8][8];
#pragma unroll
    for (int u = 0; u < 8; ++u)
#pragma unroll
        for (int p = 0; p < 8; ++p) acc[u][p] = 0ull;

    const int wrow = rt * 128 + tid;
    for (int kc = 0; kc < K; kc += CHUNK) {
        const float* xsrc = xin + ((size_t)t * K + kc) * Bn;
        for (int i = tid; i < CHUNK * 32; i += 128)
            *(float4*)(s_x + i * 4) = *(const float4*)(xsrc + i * 4);
        {
            const float* wsrc = W + (size_t)wrow * K + kc;
#pragma unroll
            for (int k4 = 0; k4 < CHUNK / 4; ++k4) {
                float4 v = *(const float4*)(wsrc + k4 * 4);
                s_w[(k4 * 4 + 0) * XP_SW_STRIDE + tid] = v.x;
                s_w[(k4 * 4 + 1) * XP_SW_STRIDE + tid] = v.y;
                s_w[(k4 * 4 + 2) * XP_SW_STRIDE + tid] = v.z;
                s_w[(k4 * 4 + 3) * XP_SW_STRIDE + tid] = v.w;
            }
        }
        __syncthreads();

#pragma unroll 2
        for (int kk = 0; kk < CHUNK; ++kk) {
            float4 wa = *(const float4*)(s_w + kk * XP_SW_STRIDE + rg * 8);
            float4 wb = *(const float4*)(s_w + kk * XP_SW_STRIDE + rg * 8 + 4);
            ull w0 = pack2(wa.x), w1 = pack2(wa.y), w2 = pack2(wa.z), w3 = pack2(wa.w);
            ull w4 = pack2(wb.x), w5 = pack2(wb.y), w6 = pack2(wb.z), w7 = pack2(wb.w);
            const float* xp = s_x + kk * Bn + bgp * 16;
            ulonglong2 x0 = *(const ulonglong2*)(xp);
            ulonglong2 x1 = *(const ulonglong2*)(xp + 4);
            ulonglong2 x2 = *(const ulonglong2*)(xp + 8);
            ulonglong2 x3 = *(const ulonglong2*)(xp + 12);
            ull xv[8] = {x0.x, x0.y, x1.x, x1.y, x2.x, x2.y, x3.x, x3.y};
#define ROW(U, WV) \
            ffma2(acc[U][0], WV, xv[0]); ffma2(acc[U][1], WV, xv[1]); \
            ffma2(acc[U][2], WV, xv[2]); ffma2(acc[U][3], WV, xv[3]); \
            ffma2(acc[U][4], WV, xv[4]); ffma2(acc[U][5], WV, xv[5]); \
            ffma2(acc[U][6], WV, xv[6]); ffma2(acc[U][7], WV, xv[7]);
            ROW(0, w0) ROW(1, w1) ROW(2, w2) ROW(3, w3)
            ROW(4, w4) ROW(5, w5) ROW(6, w6) ROW(7, w7)
#undef ROW
        }
        __syncthreads();
    }

#pragma unroll
    for (int u = 0; u < 8; ++u) {
        int grow = rt * 128 + rg * 8 + u;
        ull bb = pack2(bih[grow] + bhh[grow]);
        float* dst = gout + ((size_t)t * 1024 + grow) * Bn + bgp * 16;
#pragma unroll
        for (int p = 0; p < 8; ++p) fadd2(acc[u][p], bb);
        *(ulonglong2*)(dst)      = make_ulonglong2(acc[u][0], acc[u][1]);
        *(ulonglong2*)(dst + 4)  = make_ulonglong2(acc[u][2], acc[u][3]);
        *(ulonglong2*)(dst + 8)  = make_ulonglong2(acc[u][4], acc[u][5]);
        *(ulonglong2*)(dst + 12) = make_ulonglong2(acc[u][6], acc[u][7]);
    }
}

// ================= recurrent phase: (dir x bg x hs) partitioning =================
// 128 blocks: dir = bid>>6, bg = (bid>>3)&7 (16 batches), hs = bid&7 (32 units)
// barrier group = bid>>3 (8 blocks sharing (dir,bg))
// 256 threads: kg = tid>>6 (64 k each), rg = (tid&63)>>2 (8 gate-rows), bq = tid&3 (4 batches)
// smem (floats): s_w [256 k][132 rows-pad]; s_h [256][16]; s_gx [128 r][16];
//                s_part [4 kg][128 r][16]; s_g [128 r][16]
#define RC_SW_STRIDE 132
#define RC_SW_FLOATS (256 * RC_SW_STRIDE)       // 33792
#define RC_SH_OFF    RC_SW_FLOATS               // 4096
#define RC_SGX_OFF   (RC_SH_OFF + 4096)         // 2048
#define RC_SPART_OFF (RC_SGX_OFF + 2048)        // 8192
#define RC_SG_OFF    (RC_SPART_OFF + 8192)      // 2048
#define RC_SMEM_FLOATS (RC_SG_OFF + 2048)       // 50176 floats = 200704 B

template<bool L0P>
__global__ void __launch_bounds__(NTHR, 1) rec_kernel(
    const float* __restrict__ Whhf, const float* __restrict__ Whhb,
    const int* __restrict__ lengths)
{
    extern __shared__ float sm[];
    float* s_w    = sm;
    float* s_h    = sm + RC_SH_OFF;
    float* s_gx   = sm + RC_SGX_OFF;
    float* s_part = sm + RC_SPART_OFF;
    float* s_g    = sm + RC_SG_OFF;

    const int tid = threadIdx.x;
    const int dir = blockIdx.x >> 6;
    const int bg  = (blockIdx.x >> 3) & 7;
    const int hs  = blockIdx.x & 7;
    const int grp = blockIdx.x >> 3;
    const int kg  = tid >> 6;
    const int lid = tid & 63;
    const int rg  = lid >> 2;          // 0..15, 8 gate-rows each
    const int bq  = lid & 3;           // 0..3, 4 batches each (2 f32x2 pairs)

    const float* Whh = dir ? Whhb : Whhf;
    const float* gxb = dir ? g_gx1 : g_gx0;

    // ---- stage Whh slice: s_w[k][r] = Whh[grow(r)][k], r=0..127 local gate rows ----
    // grow(r) = (r>>5)*Hn + hs*32 + (r&31)   (gate-major PyTorch layout)
    for (int i = tid; i < 128 * 64; i += NTHR) {
        int r  = i >> 6;
        int k4 = (i & 63) * 4;
        int grow = (r >> 5) * Hn + hs * 32 + (r & 31);
        float4 v = *(const float4*)(Whh + (size_t)grow * Hn + k4);
        s_w[(k4 + 0) * RC_SW_STRIDE + r] = v.x;
        s_w[(k4 + 1) * RC_SW_STRIDE + r] = v.y;
        s_w[(k4 + 2) * RC_SW_STRIDE + r] = v.z;
        s_w[(k4 + 3) * RC_SW_STRIDE + r] = v.w;
    }

    // ---- zero own g_h slice, both parities ----
#pragma unroll
    for (int i = 0; i < 2; ++i) {
        int c = tid + i * NTHR;                 // 0..511: u = c>>4, b = c&15
        __stcg(&g_h[0][dir][bg][hs * 512 + c], 0.0f);
        __stcg(&g_h[1][dir][bg][hs * 512 + c], 0.0f);
    }

    // ---- per-thread state: 2 cells (tid, tid+256); same b, u differs by 16 ----
    float c_reg[2] = {0.0f, 0.0f};
    float h_reg[2] = {0.0f, 0.0f};
    const int len = lengths[bg * 16 + (tid & 15)];

    unsigned r_last = ld_acquire(&g_relg[grp]);

    // ---- prefetch gx for step 0 ----
    {
        int t0 = dir ? (Tn - 1) : 0;
        const float* gxrow = gxb + (size_t)t0 * 1024 * Bn;
        for (int i = tid; i < 512; i += NTHR) {
            int r = i >> 2, b4 = (i & 3) * 4;
            int grow = (r >> 5) * Hn + hs * 32 + (r & 31);
            cp_async16(s_gx + r * 16 + b4, gxrow + (size_t)grow * Bn + bg * 16 + b4);
        }
        cp_commit();
    }

    gbar_grp(grp, r_last);

    for (int s = 0; s < Tn; ++s) {
        const int t = dir ? (Tn - 1 - s) : s;

        // ---- stage h [256 k][16 b] (contiguous 16 KB) ----
        {
            const float* hsrc = &g_h[s & 1][dir][bg][0];
            for (int i = tid; i < 1024; i += NTHR)
                cp_async16(s_h + i * 4, hsrc + i * 4);
            cp_commit();
        }
        cp_wait0();          // h + (previously committed) gx
        __syncthreads();

        // ---- gates partials over own k quarter ----
        ull acc[8][2];
#pragma unroll
        for (int u = 0; u < 8; ++u) { acc[u][0] = 0ull; acc[u][1] = 0ull; }

#pragma unroll 4
        for (int kk = 0; kk < 64; ++kk) {
            int k = kg * 64 + kk;
            float4 wa = *(const float4*)(s_w + k * RC_SW_STRIDE + rg * 8);
            float4 wb = *(const float4*)(s_w + k * RC_SW_STRIDE + rg * 8 + 4);
            ull w0 = pack2(wa.x), w1 = pack2(wa.y), w2 = pack2(wa.z), w3 = pack2(wa.w);
            ull w4 = pack2(wb.x), w5 = pack2(wb.y), w6 = pack2(wb.z), w7 = pack2(wb.w);
            ulonglong2 hp = *(const ulonglong2*)(s_h + k * 16 + bq * 4);
            ffma2(acc[0][0], w0, hp.x); ffma2(acc[0][1], w0, hp.y);
            ffma2(acc[1][0], w1, hp.x); ffma2(acc[1][1], w1, hp.y);
            ffma2(acc[2][0], w2, hp.x); ffma2(acc[2][1], w2, hp.y);
            ffma2(acc[3][0], w3, hp.x); ffma2(acc[3][1], w3, hp.y);
            ffma2(acc[4][0], w4, hp.x); ffma2(acc[4][1], w4, hp.y);
            ffma2(acc[5][0], w5, hp.x); ffma2(acc[5][1], w5, hp.y);
            ffma2(acc[6][0], w6, hp.x); ffma2(acc[6][1], w6, hp.y);
            ffma2(acc[7][0], w7, hp.x); ffma2(acc[7][1], w7, hp.y);
        }

        // ---- store partials: s_part[kg][r][b] ----
#pragma unroll
        for (int u = 0; u < 8; ++u) {
            int r = rg * 8 + u;
            *(ulonglong2*)(s_part + (size_t)(kg * 128 + r) * 16 + bq * 4) =
                make_ulonglong2(acc[u][0], acc[u][1]);
        }
        __syncthreads();

        // ---- reduce k-groups + gx (biases folded into gx) -> s_g ----
#pragma unroll
        for (int i = 0; i < 8; ++i) {
            int idx = tid + i * NTHR;
            s_g[idx] = s_gx[idx] + s_part[idx] + s_part[2048 + idx]
                     + s_part[4096 + idx] + s_part[6144 + idx];
        }
        __syncthreads();

        // ---- prefetch gx for step s+1 (independent of h/barrier) ----
        if (s + 1 < Tn) {
            int tn = dir ? (Tn - 2 - s) : (s + 1);
            const float* gxrow = gxb + (size_t)tn * 1024 * Bn;
            for (int i = tid; i < 512; i += NTHR) {
                int r = i >> 2, b4 = (i & 3) * 4;
                int grow = (r >> 5) * Hn + hs * 32 + (r & 31);
                cp_async16(s_gx + r * 16 + b4, gxrow + (size_t)grow * Bn + bg * 16 + b4);
            }
            cp_commit();
        }

        // ---- pointwise: cells tid and tid+256 ----
#pragma unroll
        for (int i = 0; i < 2; ++i) {
            int c = tid + i * NTHR;             // u = c>>4, b = c&15
            float ig = sigmoidf_(s_g[c]);
            float fg = sigmoidf_(s_g[512 + c]);
            float gg = tanhf    (s_g[1024 + c]);
            float og = sigmoidf_(s_g[1536 + c]);
            float cn = fg * c_reg[i] + ig * gg;
            float hn = og * tanhf(cn);
            bool m = (t < len);
            c_reg[i] = m ? cn : c_reg[i];
            float hw = m ? hn : h_reg[i];
            h_reg[i] = hw;
            __stcg(&g_h[(s + 1) & 1][dir][bg][hs * 512 + c], hw);
            if (L0P)
                __stcg(&g_o0[((size_t)t * 512 + dir * Hn + hs * 32 + (c >> 4)) * Bn
                             + bg * 16 + (c & 15)], m ? hn : 0.0f);
        }

        gbar_grp(grp, r_last);
    }
}

// ---------------- FC head ----------------
__global__ void head_kernel(const float* __restrict__ fc1_w, const float* __restrict__ fc1_b,
                            const float* __restrict__ fc2_w, const float* __restrict__ fc2_b,
                            float* __restrict__ out)
{
    __shared__ float s_h[2 * Hn];
    __shared__ float s_r[256];
    int b = blockIdx.x;
    int tid = threadIdx.x;
    int bg = b >> 4, bl = b & 15;
    // final L1 states: 1024 steps -> parity 0
    for (int k = tid; k < 2 * Hn; k += 256) {
        int d = k >> 8;
        int j = k & (Hn - 1);
        s_h[k] = g_h[0][d][bg][j * 16 + bl];
    }
    __syncthreads();

    const float* wr = fc1_w + (size_t)tid * 2 * Hn;
    float sum = fc1_b[tid];
#pragma unroll 8
    for (int k = 0; k < 2 * Hn; ++k) sum += wr[k] * s_h[k];
    s_r[tid] = fmaxf(sum, 0.0f) * fc2_w[tid];
    __syncthreads();
    for (int st = 128; st > 0; st >>= 1) {
        if (tid < st) s_r[tid] += s_r[tid + st];
        __syncthreads();
    }
    if (tid == 0) out[b] = s_r[0] + fc2_b[0];
}

// ---------------- launch ----------------
extern "C" void kernel_launch(void* const* d_in, const int* in_sizes, int n_in,
                              void* d_out, int out_size)
{
    const float* x        = (const float*)d_in[0];
    const int*   lengths  = (const int*)  d_in[1];
    const float* w_ih_l0f = (const float*)d_in[2];
    const float* w_hh_l0f = (const float*)d_in[3];
    const float* b_ih_l0f = (const float*)d_in[4];
    const float* b_hh_l0f = (const float*)d_in[5];
    const float* w_ih_l0b = (const float*)d_in[6];
    const float* w_hh_l0b = (const float*)d_in[7];
    const float* b_ih_l0b = (const float*)d_in[8];
    const float* b_hh_l0b = (const float*)d_in[9];
    const float* w_ih_l1f = (const float*)d_in[10];
    const float* w_hh_l1f = (const float*)d_in[11];
    const float* b_ih_l1f = (const float*)d_in[12];
    const float* b_hh_l1f = (const float*)d_in[13];
    const float* w_ih_l1b = (const float*)d_in[14];
    const float* w_hh_l1b = (const float*)d_in[15];
    const float* b_ih_l1b = (const float*)d_in[16];
    const float* b_hh_l1b = (const float*)d_in[17];
    const float* fc1_w    = (const float*)d_in[18];
    const float* fc1_b    = (const float*)d_in[19];
    const float* fc2_w    = (const float*)d_in[20];
    const float* fc2_b    = (const float*)d_in[21];

    const int rec_smem = RC_SMEM_FLOATS * (int)sizeof(float);   // 200,704 B

    cudaFuncSetAttribute((const void*)rec_kernel<true>,
                         cudaFuncAttributeMaxDynamicSharedMemorySize, rec_smem);
    cudaFuncSetAttribute((const void*)rec_kernel<false>,
                         cudaFuncAttributeMaxDynamicSharedMemorySize, rec_smem);

    transpose_x_kernel<<<(Tn * Dn * Bn + 255) / 256, 256>>>(x);

    dim3 xpgrid(Tn, 8, 2);

    // layer-0 x-projection: g_xT -> g_gx
    xproj_kernel<48, 16, false><<<xpgrid, 128>>>(
        w_ih_l0f, w_ih_l0b, b_ih_l0f, b_hh_l0f, b_ih_l0b, b_hh_l0b);

    // layer-0 recurrence (h-only, consumes gx, writes g_o0)
    rec_kernel<true><<<NBLK, NTHR, rec_smem>>>(w_hh_l0f, w_hh_l0b, lengths);

    // layer-1 x-projection: g_o0 -> g_gx
    xproj_kernel<512, 32, true><<<xpgrid, 128>>>(
        w_ih_l1f, w_ih_l1b, b_ih_l1f, b_hh_l1f, b_ih_l1b, b_hh_l1b);

    // layer-1 recurrence (h-only, consumes gx)
    rec_kernel<false><<<NBLK, NTHR, rec_smem>>>(w_hh_l1f, w_hh_l1b, lengths);

    head_kernel<<<Bn, 256>>>(fc1_w, fc1_b, fc2_w, fc2_b, (float*)d_out);
}